// round 3
// baseline (speedup 1.0000x reference)
#include <cuda_runtime.h>
#include <cstdint>

// Problem constants (match reference setup_inputs)
#define FEAT        128
#define NUM_GRAPHS  10000
#define MAX_ROWS    1000000

// Tuning
#define ROWS_PER_WARP   128   // avg segment length ~100 rows -> ~2.3 segs/chunk
#define WARPS_PER_BLOCK 8
#define BLOCK_THREADS   (WARPS_PER_BLOCK * 32)

// Scratch: canonical int32 segment ids (device-global, no allocation allowed)
__device__ int g_is64;
__device__ int g_batch32[MAX_ROWS];

// ---------------------------------------------------------------------------
// Kernel 0: detect whether `batch` is int64 or int32.
// Reads only int32 words at indices < n (safe for both 4n- and 8n-byte
// buffers). Under int64 (little-endian, values < 2^31), every odd word is a
// zero high-half. Under int32 with sorted data, tail words are ~9999 != 0.
// ---------------------------------------------------------------------------
__global__ void detect_dtype_kernel(const int* __restrict__ raw, int n) {
    int lane = threadIdx.x;
    int nonzero = 0;
    // Inspect 64 odd-indexed words near the end of the safe region.
    for (int k = lane; k < 64; k += 32) {
        int idx = n - 1 - 2 * k;          // parity of n-1; step keeps parity
        if (idx > 0 && (idx & 1)) nonzero |= (raw[idx] != 0);
        idx = n - 2 - 2 * k;
        if (idx > 0 && (idx & 1)) nonzero |= (raw[idx] != 0);
    }
    nonzero = __any_sync(0xFFFFFFFF, nonzero);
    if (lane == 0) g_is64 = nonzero ? 0 : 1;
}

// ---------------------------------------------------------------------------
// Kernel 1: canonicalize batch -> int32 scratch (and compress int64 if needed)
// ---------------------------------------------------------------------------
__global__ void convert_batch_kernel(const int* __restrict__ raw, int n) {
    int is64 = g_is64;
    for (int i = blockIdx.x * blockDim.x + threadIdx.x; i < n;
         i += gridDim.x * blockDim.x) {
        g_batch32[i] = is64 ? raw[2 * i] : raw[i];
    }
}

// ---------------------------------------------------------------------------
// Kernel 2: zero the output (harness poisons d_out with 0xAA).
// ---------------------------------------------------------------------------
__global__ void zero_out_kernel(float4* __restrict__ out, int n4) {
    int i = blockIdx.x * blockDim.x + threadIdx.x;
    if (i < n4) out[i] = make_float4(0.f, 0.f, 0.f, 0.f);
}

// ---------------------------------------------------------------------------
// Kernel 3: sorted segment sum.
// One warp owns ROWS_PER_WARP contiguous rows; each lane owns 4 features
// (one float4 = one LDG.128 per row per lane). Register accumulation while
// segment id is constant; atomicAdd flush on segment change / chunk end.
// ---------------------------------------------------------------------------
__device__ __forceinline__ void flush_acc(float* __restrict__ out,
                                          int seg, int lane, const float4& acc,
                                          int max_seg) {
    if (seg < 0 || seg >= max_seg) return;  // insurance against bad ids
    float* p = out + (size_t)seg * FEAT + lane * 4;
    atomicAdd(p + 0, acc.x);
    atomicAdd(p + 1, acc.y);
    atomicAdd(p + 2, acc.z);
    atomicAdd(p + 3, acc.w);
}

__global__ __launch_bounds__(BLOCK_THREADS)
void seg_sum_kernel(const float4* __restrict__ h,   // [n_rows][32] float4
                    float* __restrict__ out,        // [max_seg][FEAT]
                    int n_rows, int max_seg) {
    const int warp_id = blockIdx.x * WARPS_PER_BLOCK + (threadIdx.x >> 5);
    const int lane    = threadIdx.x & 31;

    int start = warp_id * ROWS_PER_WARP;
    if (start >= n_rows) return;
    int end = min(start + ROWS_PER_WARP, n_rows);

    float4 acc = make_float4(0.f, 0.f, 0.f, 0.f);
    int cur = g_batch32[start];

    int r = start;
    // Unrolled x4: 4 independent LDG.128 + index loads in flight -> MLP ~ 8.
    for (; r + 4 <= end; r += 4) {
        int s0 = g_batch32[r + 0];
        int s1 = g_batch32[r + 1];
        int s2 = g_batch32[r + 2];
        int s3 = g_batch32[r + 3];
        float4 v0 = h[(size_t)(r + 0) * 32 + lane];
        float4 v1 = h[(size_t)(r + 1) * 32 + lane];
        float4 v2 = h[(size_t)(r + 2) * 32 + lane];
        float4 v3 = h[(size_t)(r + 3) * 32 + lane];

        if (s0 != cur) { flush_acc(out, cur, lane, acc, max_seg); cur = s0; acc = make_float4(0,0,0,0); }
        acc.x += v0.x; acc.y += v0.y; acc.z += v0.z; acc.w += v0.w;
        if (s1 != cur) { flush_acc(out, cur, lane, acc, max_seg); cur = s1; acc = make_float4(0,0,0,0); }
        acc.x += v1.x; acc.y += v1.y; acc.z += v1.z; acc.w += v1.w;
        if (s2 != cur) { flush_acc(out, cur, lane, acc, max_seg); cur = s2; acc = make_float4(0,0,0,0); }
        acc.x += v2.x; acc.y += v2.y; acc.z += v2.z; acc.w += v2.w;
        if (s3 != cur) { flush_acc(out, cur, lane, acc, max_seg); cur = s3; acc = make_float4(0,0,0,0); }
        acc.x += v3.x; acc.y += v3.y; acc.z += v3.z; acc.w += v3.w;
    }
    // Tail
    for (; r < end; ++r) {
        int s = g_batch32[r];
        float4 v = h[(size_t)r * 32 + lane];
        if (s != cur) { flush_acc(out, cur, lane, acc, max_seg); cur = s; acc = make_float4(0,0,0,0); }
        acc.x += v.x; acc.y += v.y; acc.z += v.z; acc.w += v.w;
    }
    // Final flush
    flush_acc(out, cur, lane, acc, max_seg);
}

// ---------------------------------------------------------------------------
// Launch. Inputs: h_t (float32, N*FEAT) and batch (int32 or int64, N).
// Order disambiguated by element count (h_t is FEAT x larger).
// ---------------------------------------------------------------------------
extern "C" void kernel_launch(void* const* d_in, const int* in_sizes, int n_in,
                              void* d_out, int out_size) {
    int hi = 0, bi = 1;
    if (n_in >= 2 && in_sizes[0] < in_sizes[1]) { hi = 1; bi = 0; }

    const float4* h        = (const float4*)d_in[hi];
    const int*    batchRaw = (const int*)d_in[bi];
    float*        out      = (float*)d_out;

    int n_rows = in_sizes[bi];
    if (n_rows > MAX_ROWS) n_rows = MAX_ROWS;
    const int max_seg = out_size / FEAT;

    // 0) dtype detect + 1) canonicalize indices
    detect_dtype_kernel<<<1, 32>>>(batchRaw, n_rows);
    convert_batch_kernel<<<256, 256>>>(batchRaw, n_rows);

    // 2) zero output
    int n4 = out_size / 4;
    zero_out_kernel<<<(n4 + 255) / 256, 256>>>((float4*)d_out, n4);

    // 3) segment sum
    int n_warps  = (n_rows + ROWS_PER_WARP - 1) / ROWS_PER_WARP;
    int n_blocks = (n_warps + WARPS_PER_BLOCK - 1) / WARPS_PER_BLOCK;
    seg_sum_kernel<<<n_blocks, BLOCK_THREADS>>>(h, out, n_rows, max_seg);
}

// round 4
// speedup vs baseline: 1.1998x; 1.1998x over previous
#include <cuda_runtime.h>
#include <cstdint>

// Problem constants (match reference setup_inputs)
#define FEAT        128
#define NUM_GRAPHS  10000

// Tuning
#define ROWS_PER_WARP   128   // avg segment length ~100 rows -> ~2.3 segs/chunk
#define WARPS_PER_BLOCK 8
#define BLOCK_THREADS   (WARPS_PER_BLOCK * 32)

// Device-global flag: element stride of the batch buffer in int32 words
// (1 = int32 indices, 2 = int64 indices, low word read).
__device__ int g_idx_stride;

// ---------------------------------------------------------------------------
// Kernel 0: detect whether `batch` is int64 or int32.
// Reads only int32 words at indices < n (safe for both 4n- and 8n-byte
// buffers). Under little-endian int64 with values < 2^31, every odd word is a
// zero high-half. Under int32 with sorted data, tail words are ~9999 != 0.
// ---------------------------------------------------------------------------
__global__ void detect_dtype_kernel(const int* __restrict__ raw, int n) {
    int lane = threadIdx.x;
    int nonzero = 0;
    for (int k = lane; k < 64; k += 32) {
        int idx = n - 1 - 2 * k;
        if (idx > 0 && (idx & 1)) nonzero |= (raw[idx] != 0);
        idx = n - 2 - 2 * k;
        if (idx > 0 && (idx & 1)) nonzero |= (raw[idx] != 0);
    }
    nonzero = __any_sync(0xFFFFFFFF, nonzero);
    if (lane == 0) g_idx_stride = nonzero ? 1 : 2;
}

// ---------------------------------------------------------------------------
// Kernel 1: zero the output (harness poisons d_out with 0xAA).
// ---------------------------------------------------------------------------
__global__ void zero_out_kernel(float4* __restrict__ out, int n4) {
    int i = blockIdx.x * blockDim.x + threadIdx.x;
    if (i < n4) out[i] = make_float4(0.f, 0.f, 0.f, 0.f);
}

// ---------------------------------------------------------------------------
// Kernel 2: sorted segment sum.
// One warp owns ROWS_PER_WARP contiguous rows; each lane owns 4 features
// (one LDG.128 per row per lane). Register accumulation while the segment id
// is constant; atomicAdd flush on segment change / chunk end. Unrolled x8 so
// 8 independent LDG.128 are in flight per warp before any consumption.
// ---------------------------------------------------------------------------
__device__ __forceinline__ void flush_acc(float* __restrict__ out,
                                          int seg, int lane, const float4& acc,
                                          int max_seg) {
    if (seg < 0 || seg >= max_seg) return;  // insurance against bad ids
    float* p = out + (size_t)seg * FEAT + lane * 4;
    atomicAdd(p + 0, acc.x);
    atomicAdd(p + 1, acc.y);
    atomicAdd(p + 2, acc.z);
    atomicAdd(p + 3, acc.w);
}

#define ACC_STEP(S, V)                                                        \
    do {                                                                      \
        if ((S) != cur) {                                                     \
            flush_acc(out, cur, lane, acc, max_seg);                          \
            cur = (S);                                                        \
            acc = make_float4(0.f, 0.f, 0.f, 0.f);                            \
        }                                                                     \
        acc.x += (V).x; acc.y += (V).y; acc.z += (V).z; acc.w += (V).w;       \
    } while (0)

__global__ __launch_bounds__(BLOCK_THREADS)
void seg_sum_kernel(const float4* __restrict__ h,     // [n_rows][32] float4
                    const int* __restrict__ braw,     // batch, stride words
                    float* __restrict__ out,          // [max_seg][FEAT]
                    int n_rows, int max_seg) {
    const int warp_id = blockIdx.x * WARPS_PER_BLOCK + (threadIdx.x >> 5);
    const int lane    = threadIdx.x & 31;
    const int stride  = g_idx_stride;  // 1 (int32) or 2 (int64 low word)

    int start = warp_id * ROWS_PER_WARP;
    if (start >= n_rows) return;
    int end = min(start + ROWS_PER_WARP, n_rows);

    float4 acc = make_float4(0.f, 0.f, 0.f, 0.f);
    int cur = braw[start * stride];

    int r = start;
    for (; r + 8 <= end; r += 8) {
        int s0 = braw[(r + 0) * stride];
        int s1 = braw[(r + 1) * stride];
        int s2 = braw[(r + 2) * stride];
        int s3 = braw[(r + 3) * stride];
        int s4 = braw[(r + 4) * stride];
        int s5 = braw[(r + 5) * stride];
        int s6 = braw[(r + 6) * stride];
        int s7 = braw[(r + 7) * stride];
        float4 v0 = h[(size_t)(r + 0) * 32 + lane];
        float4 v1 = h[(size_t)(r + 1) * 32 + lane];
        float4 v2 = h[(size_t)(r + 2) * 32 + lane];
        float4 v3 = h[(size_t)(r + 3) * 32 + lane];
        float4 v4 = h[(size_t)(r + 4) * 32 + lane];
        float4 v5 = h[(size_t)(r + 5) * 32 + lane];
        float4 v6 = h[(size_t)(r + 6) * 32 + lane];
        float4 v7 = h[(size_t)(r + 7) * 32 + lane];

        ACC_STEP(s0, v0);
        ACC_STEP(s1, v1);
        ACC_STEP(s2, v2);
        ACC_STEP(s3, v3);
        ACC_STEP(s4, v4);
        ACC_STEP(s5, v5);
        ACC_STEP(s6, v6);
        ACC_STEP(s7, v7);
    }
    // Tail
    for (; r < end; ++r) {
        int s = braw[r * stride];
        float4 v = h[(size_t)r * 32 + lane];
        ACC_STEP(s, v);
    }
    // Final flush
    flush_acc(out, cur, lane, acc, max_seg);
}

// ---------------------------------------------------------------------------
// Launch. Inputs: h_t (float32, N*FEAT) and batch (int32 or int64, N).
// Order disambiguated by element count (h_t is FEAT x larger).
// ---------------------------------------------------------------------------
extern "C" void kernel_launch(void* const* d_in, const int* in_sizes, int n_in,
                              void* d_out, int out_size) {
    int hi = 0, bi = 1;
    if (n_in >= 2 && in_sizes[0] < in_sizes[1]) { hi = 1; bi = 0; }

    const float4* h        = (const float4*)d_in[hi];
    const int*    batchRaw = (const int*)d_in[bi];
    float*        out      = (float*)d_out;

    const int n_rows  = in_sizes[bi];
    const int max_seg = out_size / FEAT;

    // 0) dtype detect (tiny)
    detect_dtype_kernel<<<1, 32>>>(batchRaw, n_rows);

    // 1) zero output (1.28M floats)
    int n4 = out_size / 4;
    zero_out_kernel<<<(n4 + 255) / 256, 256>>>((float4*)d_out, n4);

    // 2) segment sum
    int n_warps  = (n_rows + ROWS_PER_WARP - 1) / ROWS_PER_WARP;
    int n_blocks = (n_warps + WARPS_PER_BLOCK - 1) / WARPS_PER_BLOCK;
    seg_sum_kernel<<<n_blocks, BLOCK_THREADS>>>(h, batchRaw, out, n_rows, max_seg);
}

// round 5
// speedup vs baseline: 1.3107x; 1.0925x over previous
#include <cuda_runtime.h>
#include <cstdint>

// Problem constants (match reference setup_inputs)
#define FEAT        128
#define NUM_GRAPHS  10000

// Tuning
#define ROWS_PER_WARP   128   // avg segment length ~100 rows -> ~2.3 segs/chunk
#define WARPS_PER_BLOCK 8
#define BLOCK_THREADS   (WARPS_PER_BLOCK * 32)

// Device-global flag: element stride of the batch buffer in int32 words
// (1 = int32 indices, 2 = int64 indices, low word read).
__device__ int g_idx_stride;

// ---------------------------------------------------------------------------
// Kernel 1 (prologue): zero the output AND detect the batch dtype.
// Zeroing: grid-stride over float4s. Detection (block 0, warp 0 only):
// read 32 odd-indexed int32 words near the end of the n-word-safe region.
// Little-endian int64 with values < 2^31 -> odd words are all-zero high
// halves. int32 sorted data -> tail values ~9999 != 0.
// ---------------------------------------------------------------------------
__global__ void prologue_kernel(float4* __restrict__ out, int n4,
                                const int* __restrict__ braw, int n) {
    if (blockIdx.x == 0 && threadIdx.x < 32) {
        int lane = threadIdx.x;
        int idx = n - 1 - 2 * lane;          // fixed parity stepping
        if (!(idx & 1)) idx -= 1;            // force odd index
        int nonzero = (idx > 0) ? (braw[idx] != 0) : 0;
        nonzero = __any_sync(0xFFFFFFFF, nonzero);
        if (lane == 0) g_idx_stride = nonzero ? 1 : 2;
    }
    int i = blockIdx.x * blockDim.x + threadIdx.x;
    if (i < n4) out[i] = make_float4(0.f, 0.f, 0.f, 0.f);
}

// ---------------------------------------------------------------------------
// Kernel 2: sorted segment sum.
// One warp owns ROWS_PER_WARP contiguous rows; each lane owns 4 features
// (one LDG.128 per row per lane, streaming / evict-first). Register
// accumulation while the segment id is constant; atomicAdd flush on segment
// change / chunk end. Unrolled x8 -> 8 independent LDG.128 in flight per warp.
// ---------------------------------------------------------------------------
__device__ __forceinline__ void flush_acc(float* __restrict__ out,
                                          int seg, int lane, const float4& acc,
                                          int max_seg) {
    if (seg < 0 || seg >= max_seg) return;  // insurance against bad ids
    float* p = out + (size_t)seg * FEAT + lane * 4;
    atomicAdd(p + 0, acc.x);
    atomicAdd(p + 1, acc.y);
    atomicAdd(p + 2, acc.z);
    atomicAdd(p + 3, acc.w);
}

#define ACC_STEP(S, V)                                                        \
    do {                                                                      \
        if ((S) != cur) {                                                     \
            flush_acc(out, cur, lane, acc, max_seg);                          \
            cur = (S);                                                        \
            acc = make_float4(0.f, 0.f, 0.f, 0.f);                            \
        }                                                                     \
        acc.x += (V).x; acc.y += (V).y; acc.z += (V).z; acc.w += (V).w;       \
    } while (0)

__global__ __launch_bounds__(BLOCK_THREADS)
void seg_sum_kernel(const float4* __restrict__ h,     // [n_rows][32] float4
                    const int* __restrict__ braw,     // batch, stride words
                    float* __restrict__ out,          // [max_seg][FEAT]
                    int n_rows, int max_seg) {
    const int warp_id = blockIdx.x * WARPS_PER_BLOCK + (threadIdx.x >> 5);
    const int lane    = threadIdx.x & 31;
    const int stride  = g_idx_stride;  // 1 (int32) or 2 (int64 low word)

    int start = warp_id * ROWS_PER_WARP;
    if (start >= n_rows) return;
    int end = min(start + ROWS_PER_WARP, n_rows);

    float4 acc = make_float4(0.f, 0.f, 0.f, 0.f);
    int cur = braw[start * stride];

    int r = start;
    for (; r + 8 <= end; r += 8) {
        int s0 = braw[(r + 0) * stride];
        int s1 = braw[(r + 1) * stride];
        int s2 = braw[(r + 2) * stride];
        int s3 = braw[(r + 3) * stride];
        int s4 = braw[(r + 4) * stride];
        int s5 = braw[(r + 5) * stride];
        int s6 = braw[(r + 6) * stride];
        int s7 = braw[(r + 7) * stride];
        float4 v0 = __ldcs(&h[(size_t)(r + 0) * 32 + lane]);
        float4 v1 = __ldcs(&h[(size_t)(r + 1) * 32 + lane]);
        float4 v2 = __ldcs(&h[(size_t)(r + 2) * 32 + lane]);
        float4 v3 = __ldcs(&h[(size_t)(r + 3) * 32 + lane]);
        float4 v4 = __ldcs(&h[(size_t)(r + 4) * 32 + lane]);
        float4 v5 = __ldcs(&h[(size_t)(r + 5) * 32 + lane]);
        float4 v6 = __ldcs(&h[(size_t)(r + 6) * 32 + lane]);
        float4 v7 = __ldcs(&h[(size_t)(r + 7) * 32 + lane]);

        ACC_STEP(s0, v0);
        ACC_STEP(s1, v1);
        ACC_STEP(s2, v2);
        ACC_STEP(s3, v3);
        ACC_STEP(s4, v4);
        ACC_STEP(s5, v5);
        ACC_STEP(s6, v6);
        ACC_STEP(s7, v7);
    }
    // Tail
    for (; r < end; ++r) {
        int s = braw[r * stride];
        float4 v = __ldcs(&h[(size_t)r * 32 + lane]);
        ACC_STEP(s, v);
    }
    // Final flush
    flush_acc(out, cur, lane, acc, max_seg);
}

// ---------------------------------------------------------------------------
// Launch. Inputs: h_t (float32, N*FEAT) and batch (int32 or int64, N).
// Order disambiguated by element count (h_t is FEAT x larger).
// ---------------------------------------------------------------------------
extern "C" void kernel_launch(void* const* d_in, const int* in_sizes, int n_in,
                              void* d_out, int out_size) {
    int hi = 0, bi = 1;
    if (n_in >= 2 && in_sizes[0] < in_sizes[1]) { hi = 1; bi = 0; }

    const float4* h        = (const float4*)d_in[hi];
    const int*    batchRaw = (const int*)d_in[bi];
    float*        out      = (float*)d_out;

    const int n_rows  = in_sizes[bi];
    const int max_seg = out_size / FEAT;

    // 1) fused zero + dtype detect
    int n4 = out_size / 4;
    prologue_kernel<<<(n4 + 255) / 256, 256>>>((float4*)d_out, n4,
                                               batchRaw, n_rows);

    // 2) segment sum
    int n_warps  = (n_rows + ROWS_PER_WARP - 1) / ROWS_PER_WARP;
    int n_blocks = (n_warps + WARPS_PER_BLOCK - 1) / WARPS_PER_BLOCK;
    seg_sum_kernel<<<n_blocks, BLOCK_THREADS>>>(h, batchRaw, out, n_rows, max_seg);
}